// round 5
// baseline (speedup 1.0000x reference)
#include <cuda_runtime.h>
#include <math.h>

// Problem constants
constexpr int BSZ = 64;     // batch
constexpr int SEQ = 512;    // sequence length
constexpr int IN  = 512;    // input dim
constexpr int HD  = 1024;   // hidden dim
constexpr int G4  = 4 * HD; // 4096 gate columns

constexpr int NCTAS = 128;  // persistent grid (1 CTA per SM, 148 SMs available)
constexpr int NTHR  = 256;

// Scratch: xg = x @ Xcat + bcat, layout [m = b*SEQ + t][gate*HD + j]
__device__ float g_xg[(size_t)BSZ * SEQ * G4];   // 512 MB
__device__ float g_h[BSZ * HD];
__device__ unsigned g_count;
__device__ unsigned g_phase;

// Dynamic SMEM layout (floats):
//   Bs: [1024][32]            @ 0       (131072 B) -- Hcat slice, loaded once
//   As: [2][64][68] dup pairs @ 32768 f (34816 B)  -- double-buffered h chunks,
//                                                      each value stored {v,v}
//   Gs: [64][36]              @ 41472 f (9216 B)   -- g tile for epilogue
constexpr int AS_STRIDE = 68;            // floats per row (16B aligned, bank-spread)
constexpr int AS_BUF    = 64 * AS_STRIDE;
constexpr int F_BS = 0;
constexpr int F_AS = 32768;
constexpr int F_GS = F_AS + 2 * AS_BUF;  // 32768 + 8704 = 41472
constexpr int SMEM_TOTAL = (F_GS + 64 * 36) * 4;   // 175104 B

// ---------------------------------------------------------------------------
// Zero h and barrier state
// ---------------------------------------------------------------------------
__global__ void init_state_kernel() {
    int i = blockIdx.x * blockDim.x + threadIdx.x;
    if (i < BSZ * HD) g_h[i] = 0.0f;
    if (i == 0) { g_count = 0u; g_phase = 0u; }
}

// ---------------------------------------------------------------------------
// Input projection: xg[m, gate*HD + n] = sum_k x[m,k] * Xg[k,n] + bg[n]
// ---------------------------------------------------------------------------
__global__ __launch_bounds__(256, 4)
void xproj_kernel(const float* __restrict__ x,
                  const float* __restrict__ X1, const float* __restrict__ X2,
                  const float* __restrict__ X3, const float* __restrict__ X4,
                  const float* __restrict__ b1, const float* __restrict__ b2,
                  const float* __restrict__ b3, const float* __restrict__ b4)
{
    const int gate = blockIdx.z;
    const float* __restrict__ Xg = (gate == 0) ? X1 : (gate == 1) ? X2 : (gate == 2) ? X3 : X4;
    const float* __restrict__ bg = (gate == 0) ? b1 : (gate == 1) ? b2 : (gate == 2) ? b3 : b4;

    const int m0 = blockIdx.y * 64;
    const int n0 = blockIdx.x * 64;

    __shared__ float As[16][64];
    __shared__ float Bs[16][64];

    const int tid = threadIdx.x;
    const int tx = tid & 15;
    const int ty = tid >> 4;

    float acc[4][4];
    #pragma unroll
    for (int r = 0; r < 4; r++)
        #pragma unroll
        for (int c = 0; c < 4; c++) acc[r][c] = 0.0f;

    for (int k0 = 0; k0 < IN; k0 += 16) {
        {
            int row = tid >> 2;
            int kq  = tid & 3;
            float4 v = *(const float4*)(x + (size_t)(m0 + row) * IN + k0 + kq * 4);
            As[kq * 4 + 0][row] = v.x;
            As[kq * 4 + 1][row] = v.y;
            As[kq * 4 + 2][row] = v.z;
            As[kq * 4 + 3][row] = v.w;
        }
        {
            int kr = tid >> 4;
            int nq = tid & 15;
            float4 v = *(const float4*)(Xg + (size_t)(k0 + kr) * HD + n0 + nq * 4);
            *(float4*)&Bs[kr][nq * 4] = v;
        }
        __syncthreads();

        #pragma unroll
        for (int k = 0; k < 16; k++) {
            float a[4], b[4];
            #pragma unroll
            for (int r = 0; r < 4; r++) a[r] = As[k][ty * 4 + r];
            #pragma unroll
            for (int c = 0; c < 4; c++) b[c] = Bs[k][tx * 4 + c];
            #pragma unroll
            for (int r = 0; r < 4; r++)
                #pragma unroll
                for (int c = 0; c < 4; c++)
                    acc[r][c] = fmaf(a[r], b[c], acc[r][c]);
        }
        __syncthreads();
    }

    #pragma unroll
    for (int r = 0; r < 4; r++) {
        int m = m0 + ty * 4 + r;
        size_t base = (size_t)m * G4 + (size_t)gate * HD + n0;
        #pragma unroll
        for (int c = 0; c < 4; c++) {
            int n = tx * 4 + c;
            g_xg[base + n] = acc[r][c] + bg[n0 + n];
        }
    }
}

// ---------------------------------------------------------------------------
// Software grid barrier (all NCTAS CTAs resident by construction: 1 CTA/SM)
// ---------------------------------------------------------------------------
__device__ __forceinline__ void grid_sync(unsigned target) {
    __syncthreads();
    if (threadIdx.x == 0) {
        __threadfence();                      // publish h stores
        if (atomicAdd(&g_count, 1u) == NCTAS - 1) {
            atomicExch(&g_count, 0u);
            __threadfence();
            atomicExch(&g_phase, target);
        } else {
            while (atomicAdd(&g_phase, 0u) < target) { __nanosleep(64); }
        }
        __threadfence();                      // invalidate L1 so fresh h is read
    }
    __syncthreads();
}

// ---------------------------------------------------------------------------
// Persistent recurrence kernel: all 512 timesteps in one launch.
// Each CTA owns 8 hidden columns (x 4 gates = 32 N-cols) for all 64 batch rows.
//  - Hcat slice cached in SMEM once (128 KB), reused for all steps
//  - c state in registers (exclusive ownership)
//  - h streamed through double-buffered SMEM, stored as duplicated {v,v} pairs
//    so the FFMA2 broadcast operand is one ld.shared.b64 (no packs)
//  - 256 threads (2 warps/SMSP) for latency hiding; thread tile 2x4
// ---------------------------------------------------------------------------
__global__ void __launch_bounds__(NTHR, 1)
lstm_persistent_kernel(const float* __restrict__ H1, const float* __restrict__ H2,
                       const float* __restrict__ H3, const float* __restrict__ H4,
                       float* __restrict__ out)
{
    extern __shared__ float smem[];
    float* Bs = smem + F_BS;     // [k][c], c = gate*8 + jj, stride 32
    float* As = smem + F_AS;     // [buf][row][kk dup pairs], stride AS_STRIDE
    float* Gs = smem + F_GS;     // [row][col], stride 36

    const int tid = threadIdx.x;
    const int tx  = tid & 7;                // 4 tile-cols each
    const int ty  = tid >> 3;               // 0..31, 2 tile-rows each
    const int j0  = blockIdx.x * 8;

    // ---- Load Hcat slice (32 cols x 1024 k) into SMEM once ----
    {
        const int bk   = tid >> 3;          // 0..31 (k within chunk)
        const int bgt  = (tid >> 1) & 3;    // gate
        const int half = tid & 1;           // which float4 of the 8 cols
        const float* __restrict__ Hg = (bgt == 0) ? H1 : (bgt == 1) ? H2 : (bgt == 2) ? H3 : H4;
        for (int k0 = 0; k0 < HD; k0 += 32) {
            float4 v = *(const float4*)(Hg + (size_t)(k0 + bk) * HD + j0 + half * 4);
            *(float4*)&Bs[(k0 + bk) * 32 + bgt * 8 + half * 4] = v;
        }
    }

    const unsigned bs_u = (unsigned)__cvta_generic_to_shared(Bs);
    const unsigned as_u = (unsigned)__cvta_generic_to_shared(As);

    // ---- Per-thread epilogue slots: 2 (b, j) pairs, fixed for all steps ----
    const float* xptr[2];
    float*       hptr[2];
    float*       optr[2];
    int          goff[2];
    float        c_reg[2] = {0.f, 0.f};
    #pragma unroll
    for (int i = 0; i < 2; i++) {
        int p  = tid + NTHR * i;            // 0..511
        int b  = p >> 3;
        int jj = p & 7;
        int j  = j0 + jj;
        xptr[i] = g_xg + (size_t)b * SEQ * G4 + j;
        hptr[i] = g_h + b * HD + j;
        optr[i] = out + (size_t)b * SEQ * HD + j;
        goff[i] = b * 36 + jj;
    }

    // ---- A-staging slots: 2 float4 per thread per 64x32 chunk ----
    int aoff_g[2];                          // g_h float offset (row*HD + kq*4)
    int aoff_s[2];                          // As float offset  (row*AS_STRIDE + kq*8)
    #pragma unroll
    for (int i = 0; i < 2; i++) {
        int q   = tid + NTHR * i;           // 0..511
        int row = q >> 3;                   // 0..63
        int kq  = q & 7;                    // 0..7
        aoff_g[i] = row * HD + kq * 4;
        aoff_s[i] = row * AS_STRIDE + kq * 8;
    }

    // Compute-side A addresses (bytes): rows ty*2, ty*2+1
    const unsigned a_row0 = as_u + (unsigned)((ty * 2 + 0) * AS_STRIDE) * 4u;
    const unsigned a_row1 = as_u + (unsigned)((ty * 2 + 1) * AS_STRIDE) * 4u;
    const unsigned as_bufb = (unsigned)(AS_BUF * 4);   // buffer stride in bytes

    __syncthreads();                        // Bs ready

    for (int t = 0; t < SEQ; t++) {
        // ---- Prefetch xg (DRAM) — hides under the K loop ----
        float xf[2], xi[2], xc[2], xo[2];
        const size_t toff = (size_t)t * G4;
        #pragma unroll
        for (int i = 0; i < 2; i++) {
            const float* xp = xptr[i] + toff;
            xf[i] = __ldg(xp);
            xi[i] = __ldg(xp + HD);
            xc[i] = __ldg(xp + 2 * HD);
            xo[i] = __ldg(xp + 3 * HD);
        }

        unsigned long long acc00 = 0ull, acc01 = 0ull;  // row0: cols {0,1},{2,3}
        unsigned long long acc10 = 0ull, acc11 = 0ull;  // row1

        // ---- Prologue: stage chunk 0 (duplicated), prefetch chunk 1 ----
        float4 v[2];
        #pragma unroll
        for (int i = 0; i < 2; i++) v[i] = *(const float4*)(g_h + aoff_g[i]);
        #pragma unroll
        for (int i = 0; i < 2; i++) {
            float4 w = v[i];
            *(float4*)&As[aoff_s[i]]     = make_float4(w.x, w.x, w.y, w.y);
            *(float4*)&As[aoff_s[i] + 4] = make_float4(w.z, w.z, w.w, w.w);
        }
        #pragma unroll
        for (int i = 0; i < 2; i++) v[i] = *(const float4*)(g_h + aoff_g[i] + 32);
        __syncthreads();

        for (int ch = 0; ch < 32; ch++) {
            // Stage chunk ch+1 (duplicated) into the other buffer
            if (ch + 1 < 32) {
                const int nb = ((ch + 1) & 1) * AS_BUF;
                #pragma unroll
                for (int i = 0; i < 2; i++) {
                    float4 w = v[i];
                    *(float4*)&As[nb + aoff_s[i]]     = make_float4(w.x, w.x, w.y, w.y);
                    *(float4*)&As[nb + aoff_s[i] + 4] = make_float4(w.z, w.z, w.w, w.w);
                }
            }
            // Prefetch chunk ch+2 from global
            if (ch + 2 < 32) {
                const int gk = (ch + 2) * 32;
                #pragma unroll
                for (int i = 0; i < 2; i++) v[i] = *(const float4*)(g_h + aoff_g[i] + gk);
            }

            unsigned baddr  = bs_u + (unsigned)(ch * 1024 + tx * 4) * 4u;
            unsigned abase0 = a_row0 + (unsigned)(ch & 1) * as_bufb;
            unsigned abase1 = a_row1 + (unsigned)(ch & 1) * as_bufb;

            #pragma unroll
            for (int kk = 0; kk < 32; kk++) {
                unsigned long long b01, b23;
                asm volatile("ld.shared.v2.b64 {%0,%1},[%2];"
                             : "=l"(b01), "=l"(b23) : "r"(baddr + (unsigned)(kk * 128)));
                unsigned long long aa0, aa1;
                asm volatile("ld.shared.b64 %0,[%1];" : "=l"(aa0)
                             : "r"(abase0 + (unsigned)(kk * 8)));
                asm volatile("ld.shared.b64 %0,[%1];" : "=l"(aa1)
                             : "r"(abase1 + (unsigned)(kk * 8)));

                asm("fma.rn.f32x2 %0,%1,%2,%0;" : "+l"(acc00) : "l"(aa0), "l"(b01));
                asm("fma.rn.f32x2 %0,%1,%2,%0;" : "+l"(acc01) : "l"(aa0), "l"(b23));
                asm("fma.rn.f32x2 %0,%1,%2,%0;" : "+l"(acc10) : "l"(aa1), "l"(b01));
                asm("fma.rn.f32x2 %0,%1,%2,%0;" : "+l"(acc11) : "l"(aa1), "l"(b23));
            }
            __syncthreads();
        }

        // ---- Stage g tile into Gs so epilogue threads can gather 4 gates ----
        {
            float f0, f1, f2, f3;
            asm("mov.b64 {%0,%1},%2;" : "=f"(f0), "=f"(f1) : "l"(acc00));
            asm("mov.b64 {%0,%1},%2;" : "=f"(f2), "=f"(f3) : "l"(acc01));
            *(float4*)&Gs[(ty * 2 + 0) * 36 + tx * 4] = make_float4(f0, f1, f2, f3);
            asm("mov.b64 {%0,%1},%2;" : "=f"(f0), "=f"(f1) : "l"(acc10));
            asm("mov.b64 {%0,%1},%2;" : "=f"(f2), "=f"(f3) : "l"(acc11));
            *(float4*)&Gs[(ty * 2 + 1) * 36 + tx * 4] = make_float4(f0, f1, f2, f3);
        }
        __syncthreads();

        // ---- Epilogue: gates, c/h update, output ----
        #pragma unroll
        for (int i = 0; i < 2; i++) {
            const int go_ = goff[i];
            float gf = Gs[go_ +  0] + xf[i];
            float gi = Gs[go_ +  8] + xi[i];
            float gc = Gs[go_ + 16] + xc[i];
            float gg = Gs[go_ + 24] + xo[i];

            float s1 = 1.0f / (1.0f + expf(-gf));
            float s2 = 1.0f / (1.0f + expf(-gi));
            float t1 = tanhf(gc);
            float s3 = 1.0f / (1.0f + expf(-gg));

            c_reg[i] = c_reg[i] * s1 + s2 * t1;
            float hnew = tanhf(c_reg[i]) * s3;

            *hptr[i] = hnew;
            optr[i][(size_t)t * HD] = hnew;
        }

        // ---- Grid-wide barrier before next step reads updated h ----
        if (t + 1 < SEQ) grid_sync((unsigned)(t + 1));
    }
}

// ---------------------------------------------------------------------------
// Launch
// ---------------------------------------------------------------------------
extern "C" void kernel_launch(void* const* d_in, const int* in_sizes, int n_in,
                              void* d_out, int out_size)
{
    const float* x  = (const float*)d_in[0];
    const float* X1 = (const float*)d_in[1];
    const float* H1 = (const float*)d_in[2];
    const float* b1 = (const float*)d_in[3];
    const float* X2 = (const float*)d_in[4];
    const float* H2 = (const float*)d_in[5];
    const float* b2 = (const float*)d_in[6];
    const float* X3 = (const float*)d_in[7];
    const float* H3 = (const float*)d_in[8];
    const float* b3 = (const float*)d_in[9];
    const float* X4 = (const float*)d_in[10];
    const float* H4 = (const float*)d_in[11];
    const float* b4 = (const float*)d_in[12];
    float* out = (float*)d_out;

    cudaFuncSetAttribute(lstm_persistent_kernel,
                         cudaFuncAttributeMaxDynamicSharedMemorySize, SMEM_TOTAL);

    // Zero recurrent state + barrier
    init_state_kernel<<<(BSZ * HD + 255) / 256, 256>>>();

    // Input projection: xg = x @ Xcat + bcat
    dim3 grid_x(HD / 64, (BSZ * SEQ) / 64, 4);
    xproj_kernel<<<grid_x, 256>>>(x, X1, X2, X3, X4, b1, b2, b3, b4);

    // Persistent recurrence: all 512 steps in one kernel
    lstm_persistent_kernel<<<NCTAS, NTHR, SMEM_TOTAL>>>(H1, H2, H3, H4, out);
}

// round 6
// speedup vs baseline: 1.2170x; 1.2170x over previous
#include <cuda_runtime.h>
#include <math.h>

// Problem constants
constexpr int BSZ = 64;     // batch
constexpr int SEQ = 512;    // sequence length
constexpr int IN  = 512;    // input dim
constexpr int HD  = 1024;   // hidden dim
constexpr int G4  = 4 * HD; // 4096 gate columns

constexpr int NCTAS = 128;  // persistent grid (1 CTA per SM)
constexpr int NTHR  = 128;

// Scratch: xg = x @ Xcat + bcat, layout [m = b*SEQ + t][gate*HD + j]
__device__ float g_xg[(size_t)BSZ * SEQ * G4];   // 512 MB
__device__ float g_h[BSZ * HD];
__device__ unsigned g_count;
__device__ unsigned g_phase;

// Dynamic SMEM layout (floats):
//   Bs: [1024][32]  @ 0        (131072 B)  -- Hcat slice, gate-interleaved
//                                             col = jj*4 + gate
//   As: [2][64][68] @ 32768 f  (34816 B)   -- double-buffered h chunks,
//                                             values stored duplicated {v,v}
constexpr int AS_STRIDE = 68;             // floats per row (272 B, 16B aligned)
constexpr int AS_BUF    = 64 * AS_STRIDE; // 4352 floats
constexpr int F_BS = 0;
constexpr int F_AS = 32768;
constexpr int SMEM_TOTAL = (F_AS + 2 * AS_BUF) * 4;   // 165888 B

#define FMA2(acc, a, b) asm("fma.rn.f32x2 %0,%1,%2,%0;" : "+l"(acc) : "l"(a), "l"(b))

// ---------------------------------------------------------------------------
// Zero h and barrier state
// ---------------------------------------------------------------------------
__global__ void init_state_kernel() {
    int i = blockIdx.x * blockDim.x + threadIdx.x;
    if (i < BSZ * HD) g_h[i] = 0.0f;
    if (i == 0) { g_count = 0u; g_phase = 0u; }
}

// ---------------------------------------------------------------------------
// Input projection: xg[m, gate*HD + n] = sum_k x[m,k] * Xg[k,n] + bg[n]
// ---------------------------------------------------------------------------
__global__ __launch_bounds__(256, 4)
void xproj_kernel(const float* __restrict__ x,
                  const float* __restrict__ X1, const float* __restrict__ X2,
                  const float* __restrict__ X3, const float* __restrict__ X4,
                  const float* __restrict__ b1, const float* __restrict__ b2,
                  const float* __restrict__ b3, const float* __restrict__ b4)
{
    const int gate = blockIdx.z;
    const float* __restrict__ Xg = (gate == 0) ? X1 : (gate == 1) ? X2 : (gate == 2) ? X3 : X4;
    const float* __restrict__ bg = (gate == 0) ? b1 : (gate == 1) ? b2 : (gate == 2) ? b3 : b4;

    const int m0 = blockIdx.y * 64;
    const int n0 = blockIdx.x * 64;

    __shared__ float As[16][64];
    __shared__ float Bs[16][64];

    const int tid = threadIdx.x;
    const int tx = tid & 15;
    const int ty = tid >> 4;

    float acc[4][4];
    #pragma unroll
    for (int r = 0; r < 4; r++)
        #pragma unroll
        for (int c = 0; c < 4; c++) acc[r][c] = 0.0f;

    for (int k0 = 0; k0 < IN; k0 += 16) {
        {
            int row = tid >> 2;
            int kq  = tid & 3;
            float4 v = *(const float4*)(x + (size_t)(m0 + row) * IN + k0 + kq * 4);
            As[kq * 4 + 0][row] = v.x;
            As[kq * 4 + 1][row] = v.y;
            As[kq * 4 + 2][row] = v.z;
            As[kq * 4 + 3][row] = v.w;
        }
        {
            int kr = tid >> 4;
            int nq = tid & 15;
            float4 v = *(const float4*)(Xg + (size_t)(k0 + kr) * HD + n0 + nq * 4);
            *(float4*)&Bs[kr][nq * 4] = v;
        }
        __syncthreads();

        #pragma unroll
        for (int k = 0; k < 16; k++) {
            float a[4], b[4];
            #pragma unroll
            for (int r = 0; r < 4; r++) a[r] = As[k][ty * 4 + r];
            #pragma unroll
            for (int c = 0; c < 4; c++) b[c] = Bs[k][tx * 4 + c];
            #pragma unroll
            for (int r = 0; r < 4; r++)
                #pragma unroll
                for (int c = 0; c < 4; c++)
                    acc[r][c] = fmaf(a[r], b[c], acc[r][c]);
        }
        __syncthreads();
    }

    #pragma unroll
    for (int r = 0; r < 4; r++) {
        int m = m0 + ty * 4 + r;
        size_t base = (size_t)m * G4 + (size_t)gate * HD + n0;
        #pragma unroll
        for (int c = 0; c < 4; c++) {
            int n = tx * 4 + c;
            g_xg[base + n] = acc[r][c] + bg[n0 + n];
        }
    }
}

// ---------------------------------------------------------------------------
// Software grid barrier (all NCTAS CTAs resident: 1 CTA/SM)
// ---------------------------------------------------------------------------
__device__ __forceinline__ void grid_sync(unsigned target) {
    __syncthreads();
    if (threadIdx.x == 0) {
        __threadfence();                      // publish h stores to L2
        if (atomicAdd(&g_count, 1u) == NCTAS - 1) {
            atomicExch(&g_count, 0u);
            __threadfence();
            atomicExch(&g_phase, target);
        } else {
            while (atomicAdd(&g_phase, 0u) < target) { __nanosleep(64); }
        }
        // no trailing L1 invalidate: all cross-CTA reads (g_h) use __ldcg (L2)
    }
    __syncthreads();
}

// ---------------------------------------------------------------------------
// Persistent recurrence kernel: all 512 timesteps in one launch.
// Each CTA owns 8 hidden columns j0..j0+7 (x 4 gates) for all 64 batch rows.
// Thread (tx=jj 0..7, ty 0..15) owns output rows {ty, ty+16, ty+32, ty+48}
// at column j0+tx; its 4 accumulator pairs hold {gf,gi} and {gc,go} directly
// (gate-interleaved B layout) -> register-only epilogue, no Gs staging.
//  - Hcat slice in SMEM once (128 KB)
//  - A (h) duplicated {v,v} pairs, conflict-free LDS.128 reads (2 kk per load)
//  - c state in registers
// ---------------------------------------------------------------------------
__global__ void __launch_bounds__(NTHR, 1)
lstm_persistent_kernel(const float* __restrict__ H1, const float* __restrict__ H2,
                       const float* __restrict__ H3, const float* __restrict__ H4,
                       float* __restrict__ out)
{
    extern __shared__ float smem[];
    float* Bs = smem + F_BS;     // [k][jj*4 + gate]
    float* As = smem + F_AS;     // [buf][row][kk dup pairs], stride AS_STRIDE

    const int tid = threadIdx.x;
    const int tx  = tid & 7;                // jj: column within the 8 owned
    const int ty  = tid >> 3;               // 0..15
    const int j0  = blockIdx.x * 8;

    // ---- Load Hcat slice into SMEM once (gate-interleaved columns) ----
    {
        const float* __restrict__ Hgs[1];   // avoid local array spill: unroll gates
        (void)Hgs;
        #pragma unroll
        for (int g = 0; g < 4; g++) {
            const float* __restrict__ Hg = (g == 0) ? H1 : (g == 1) ? H2 : (g == 2) ? H3 : H4;
            for (int idx = tid; idx < HD * 8; idx += NTHR) {
                int k  = idx >> 3;
                int jj = idx & 7;
                Bs[k * 32 + jj * 4 + g] = Hg[(size_t)k * HD + j0 + jj];
            }
        }
    }

    // ---- Per-thread epilogue slots: 4 rows {ty + 16*i}, fixed column ----
    const float* xptr[4];
    float*       hptr[4];
    float*       optr[4];
    float        c_reg[4] = {0.f, 0.f, 0.f, 0.f};
    #pragma unroll
    for (int i = 0; i < 4; i++) {
        int b = ty + 16 * i;
        int j = j0 + tx;
        xptr[i] = g_xg + (size_t)b * SEQ * G4 + j;
        hptr[i] = g_h + b * HD + j;
        optr[i] = out + (size_t)b * SEQ * HD + j;
    }

    // ---- A-staging slots: 4 float4 of g_h per thread per 64x32 chunk ----
    int aoff_g[4];                          // g_h float offset (row*HD + kq*4)
    int aoff_s[4];                          // As float offset  (row*AS_STRIDE + kq*8)
    #pragma unroll
    for (int i = 0; i < 4; i++) {
        int q   = tid + NTHR * i;           // 0..511
        int row = q >> 3;                   // 0..63
        int kq  = q & 7;                    // 0..7
        aoff_g[i] = row * HD + kq * 4;
        aoff_s[i] = row * AS_STRIDE + kq * 8;
    }

    __syncthreads();                        // Bs ready

    for (int t = 0; t < SEQ; t++) {
        // ---- Prefetch xg (read-only) — hides under the K loop ----
        float xf[4], xi[4], xc[4], xo[4];
        const size_t toff = (size_t)t * G4;
        #pragma unroll
        for (int i = 0; i < 4; i++) {
            const float* xp = xptr[i] + toff;
            xf[i] = __ldg(xp);
            xi[i] = __ldg(xp + HD);
            xc[i] = __ldg(xp + 2 * HD);
            xo[i] = __ldg(xp + 3 * HD);
        }

        // acc[r][0] = {gf,gi}, acc[r][1] = {gc,go} for row ty+16r, col j0+tx
        unsigned long long acc[4][2];
        #pragma unroll
        for (int r = 0; r < 4; r++) { acc[r][0] = 0ull; acc[r][1] = 0ull; }

        // ---- Prologue: stage chunk 0 (duplicated), prefetch chunk 1 ----
        float4 v[4];
        #pragma unroll
        for (int i = 0; i < 4; i++)
            v[i] = __ldcg((const float4*)(g_h + aoff_g[i]));
        #pragma unroll
        for (int i = 0; i < 4; i++) {
            float4 w = v[i];
            *(float4*)&As[aoff_s[i]]     = make_float4(w.x, w.x, w.y, w.y);
            *(float4*)&As[aoff_s[i] + 4] = make_float4(w.z, w.z, w.w, w.w);
        }
        #pragma unroll
        for (int i = 0; i < 4; i++)
            v[i] = __ldcg((const float4*)(g_h + aoff_g[i] + 32));
        __syncthreads();

        for (int ch = 0; ch < 32; ch++) {
            // Stage chunk ch+1 into the other buffer (safe: readers of that
            // buffer finished at the syncthreads ending chunk ch-1)
            if (ch + 1 < 32) {
                const int nb = ((ch + 1) & 1) * AS_BUF;
                #pragma unroll
                for (int i = 0; i < 4; i++) {
                    float4 w = v[i];
                    *(float4*)&As[nb + aoff_s[i]]     = make_float4(w.x, w.x, w.y, w.y);
                    *(float4*)&As[nb + aoff_s[i] + 4] = make_float4(w.z, w.z, w.w, w.w);
                }
            }
            // Prefetch chunk ch+2 from global (L2-fresh)
            if (ch + 2 < 32) {
                const int gk = (ch + 2) * 32;
                #pragma unroll
                for (int i = 0; i < 4; i++)
                    v[i] = __ldcg((const float4*)(g_h + aoff_g[i] + gk));
            }

            const float* Bb = Bs + ch * 1024 + tx * 4;
            const char*  Ab = (const char*)(As + (ch & 1) * AS_BUF);
            const ulonglong2* Ar0 = (const ulonglong2*)(Ab + (ty +  0) * 272);
            const ulonglong2* Ar1 = (const ulonglong2*)(Ab + (ty + 16) * 272);
            const ulonglong2* Ar2 = (const ulonglong2*)(Ab + (ty + 32) * 272);
            const ulonglong2* Ar3 = (const ulonglong2*)(Ab + (ty + 48) * 272);

            #pragma unroll
            for (int k2 = 0; k2 < 16; k2++) {
                // B for two consecutive k: {g0,g1} in .x, {g2,g3} in .y
                ulonglong2 b0 = *(const ulonglong2*)(Bb + (2 * k2) * 32);
                ulonglong2 b1 = *(const ulonglong2*)(Bb + (2 * k2 + 1) * 32);

                ulonglong2 a0 = Ar0[k2];   // .x = dup h[row][2k2], .y = dup h[row][2k2+1]
                FMA2(acc[0][0], a0.x, b0.x); FMA2(acc[0][1], a0.x, b0.y);
                FMA2(acc[0][0], a0.y, b1.x); FMA2(acc[0][1], a0.y, b1.y);

                ulonglong2 a1 = Ar1[k2];
                FMA2(acc[1][0], a1.x, b0.x); FMA2(acc[1][1], a1.x, b0.y);
                FMA2(acc[1][0], a1.y, b1.x); FMA2(acc[1][1], a1.y, b1.y);

                ulonglong2 a2 = Ar2[k2];
                FMA2(acc[2][0], a2.x, b0.x); FMA2(acc[2][1], a2.x, b0.y);
                FMA2(acc[2][0], a2.y, b1.x); FMA2(acc[2][1], a2.y, b1.y);

                ulonglong2 a3 = Ar3[k2];
                FMA2(acc[3][0], a3.x, b0.x); FMA2(acc[3][1], a3.x, b0.y);
                FMA2(acc[3][0], a3.y, b1.x); FMA2(acc[3][1], a3.y, b1.y);
            }
            __syncthreads();
        }

        // ---- Epilogue: register-only gates, c/h update, output ----
        #pragma unroll
        for (int i = 0; i < 4; i++) {
            float gf, gi, gc, gg;
            asm("mov.b64 {%0,%1},%2;" : "=f"(gf), "=f"(gi) : "l"(acc[i][0]));
            asm("mov.b64 {%0,%1},%2;" : "=f"(gc), "=f"(gg) : "l"(acc[i][1]));
            gf += xf[i];
            gi += xi[i];
            gc += xc[i];
            gg += xo[i];

            float s1 = 1.0f / (1.0f + expf(-gf));
            float s2 = 1.0f / (1.0f + expf(-gi));
            float t1 = tanhf(gc);
            float s3 = 1.0f / (1.0f + expf(-gg));

            c_reg[i] = c_reg[i] * s1 + s2 * t1;
            float hnew = tanhf(c_reg[i]) * s3;

            *hptr[i] = hnew;
            optr[i][(size_t)t * HD] = hnew;
        }

        // ---- Grid-wide barrier before next step reads updated h ----
        if (t + 1 < SEQ) grid_sync((unsigned)(t + 1));
    }
}

// ---------------------------------------------------------------------------
// Launch
// ---------------------------------------------------------------------------
extern "C" void kernel_launch(void* const* d_in, const int* in_sizes, int n_in,
                              void* d_out, int out_size)
{
    const float* x  = (const float*)d_in[0];
    const float* X1 = (const float*)d_in[1];
    const float* H1 = (const float*)d_in[2];
    const float* b1 = (const float*)d_in[3];
    const float* X2 = (const float*)d_in[4];
    const float* H2 = (const float*)d_in[5];
    const float* b2 = (const float*)d_in[6];
    const float* X3 = (const float*)d_in[7];
    const float* H3 = (const float*)d_in[8];
    const float* b3 = (const float*)d_in[9];
    const float* X4 = (const float*)d_in[10];
    const float* H4 = (const float*)d_in[11];
    const float* b4 = (const float*)d_in[12];
    float* out = (float*)d_out;

    cudaFuncSetAttribute(lstm_persistent_kernel,
                         cudaFuncAttributeMaxDynamicSharedMemorySize, SMEM_TOTAL);

    // Zero recurrent state + barrier
    init_state_kernel<<<(BSZ * HD + 255) / 256, 256>>>();

    // Input projection: xg = x @ Xcat + bcat
    dim3 grid_x(HD / 64, (BSZ * SEQ) / 64, 4);
    xproj_kernel<<<grid_x, 256>>>(x, X1, X2, X3, X4, b1, b2, b3, b4);

    // Persistent recurrence: all 512 steps in one kernel
    lstm_persistent_kernel<<<NCTAS, NTHR, SMEM_TOTAL>>>(H1, H2, H3, H4, out);
}